// round 1
// baseline (speedup 1.0000x reference)
#include <cuda_runtime.h>

#define NN   100000
#define EE   1600000
#define KIN  256
#define KOUT 128

// Scratch (allocation-free rule: __device__ globals)
__device__ float g_featproj[NN * KOUT];   // 51.2 MB projected features
__device__ int   g_outcnt[NN];
__device__ int   g_incnt[NN];

// ---------------------------------------------------------------------------
// Kernel 1: zero degree counters and d_out (d_out is poisoned each replay)
// ---------------------------------------------------------------------------
__global__ void k_init(float* __restrict__ out) {
    int i = blockIdx.x * blockDim.x + threadIdx.x;
    int stride = gridDim.x * blockDim.x;
    for (int j = i; j < NN; j += stride) { g_outcnt[j] = 0; g_incnt[j] = 0; }
    const int n4 = NN * KOUT / 4;
    float4 z = make_float4(0.f, 0.f, 0.f, 0.f);
    float4* o4 = reinterpret_cast<float4*>(out);
    for (int j = i; j < n4; j += stride) o4[j] = z;
}

// ---------------------------------------------------------------------------
// Kernel 2: degree histograms
// ---------------------------------------------------------------------------
__global__ void k_deg(const int* __restrict__ src, const int* __restrict__ dst) {
    int i = blockIdx.x * blockDim.x + threadIdx.x;
    if (i < EE) {
        atomicAdd(&g_outcnt[src[i]], 1);
        atomicAdd(&g_incnt[dst[i]], 1);
    }
}

// ---------------------------------------------------------------------------
// Kernel 3: FP32 SGEMM  g_featproj = diag(out_deg^-1/2) * feat @ (mask>0.5)*W
// BM=128, BN=128(=KOUT), BK=8, 256 threads, 8x8 per thread
// ---------------------------------------------------------------------------
__global__ __launch_bounds__(256) void k_gemm(const float* __restrict__ feat,
                                              const float* __restrict__ weight,
                                              const float* __restrict__ maskr) {
    __shared__ float As[8][128];   // transposed A tile: [k][m]
    __shared__ float Bs[8][128];   // [k][n]

    const int tid = threadIdx.x;
    const int blockRow = blockIdx.x * 128;

    // A-load mapping: each thread loads one float4 of one row
    const int arow = tid >> 1;
    const int acol = (tid & 1) * 4;
    const int grow = blockRow + arow;
    float scale = 0.f;
    if (grow < NN) scale = rsqrtf((float)max(g_outcnt[grow], 1));

    // B-load mapping
    const int brow = tid >> 5;
    const int bcol = (tid & 31) * 4;

    // compute mapping: 16x16 thread grid of 8x8 tiles
    const int ty = tid >> 4;
    const int tx = tid & 15;

    float acc[8][8];
#pragma unroll
    for (int i = 0; i < 8; i++)
#pragma unroll
        for (int j = 0; j < 8; j++) acc[i][j] = 0.f;

    for (int k0 = 0; k0 < KIN; k0 += 8) {
        float4 a = make_float4(0.f, 0.f, 0.f, 0.f);
        if (grow < NN)
            a = *reinterpret_cast<const float4*>(&feat[grow * KIN + k0 + acol]);
        As[acol + 0][arow] = a.x * scale;
        As[acol + 1][arow] = a.y * scale;
        As[acol + 2][arow] = a.z * scale;
        As[acol + 3][arow] = a.w * scale;

        float4 w4 = *reinterpret_cast<const float4*>(&weight[(k0 + brow) * KOUT + bcol]);
        float4 m4 = *reinterpret_cast<const float4*>(&maskr [(k0 + brow) * KOUT + bcol]);
        w4.x = (m4.x > 0.5f) ? w4.x : 0.f;
        w4.y = (m4.y > 0.5f) ? w4.y : 0.f;
        w4.z = (m4.z > 0.5f) ? w4.z : 0.f;
        w4.w = (m4.w > 0.5f) ? w4.w : 0.f;
        *reinterpret_cast<float4*>(&Bs[brow][bcol]) = w4;

        __syncthreads();

#pragma unroll
        for (int k = 0; k < 8; k++) {
            float ar[8], br[8];
            *reinterpret_cast<float4*>(&ar[0]) = *reinterpret_cast<const float4*>(&As[k][ty * 8]);
            *reinterpret_cast<float4*>(&ar[4]) = *reinterpret_cast<const float4*>(&As[k][ty * 8 + 4]);
            *reinterpret_cast<float4*>(&br[0]) = *reinterpret_cast<const float4*>(&Bs[k][tx * 8]);
            *reinterpret_cast<float4*>(&br[4]) = *reinterpret_cast<const float4*>(&Bs[k][tx * 8 + 4]);
#pragma unroll
            for (int i = 0; i < 8; i++)
#pragma unroll
                for (int j = 0; j < 8; j++)
                    acc[i][j] = fmaf(ar[i], br[j], acc[i][j]);
        }
        __syncthreads();
    }

#pragma unroll
    for (int i = 0; i < 8; i++) {
        int r = blockRow + ty * 8 + i;
        if (r < NN) {
            *reinterpret_cast<float4*>(&g_featproj[r * KOUT + tx * 8]) =
                make_float4(acc[i][0], acc[i][1], acc[i][2], acc[i][3]);
            *reinterpret_cast<float4*>(&g_featproj[r * KOUT + tx * 8 + 4]) =
                make_float4(acc[i][4], acc[i][5], acc[i][6], acc[i][7]);
        }
    }
}

// ---------------------------------------------------------------------------
// Kernel 4: edge scatter. One warp per edge: coalesced 512B gather, scale by
// edge weight, vectorized red.global.add.v4.f32 into d_out.
// ---------------------------------------------------------------------------
__global__ __launch_bounds__(256) void k_scatter(const int* __restrict__ src,
                                                 const int* __restrict__ dst,
                                                 const float* __restrict__ ew,
                                                 float* __restrict__ out) {
    long long gid = (long long)blockIdx.x * blockDim.x + threadIdx.x;
    int e = (int)(gid >> 5);
    int lane = (int)(gid & 31);
    if (e >= EE) return;

    int s = src[e];
    int d = dst[e];
    float w = ew[e];

    float4 v = *reinterpret_cast<const float4*>(&g_featproj[s * KOUT + lane * 4]);
    float* p = &out[(long long)d * KOUT + lane * 4];
    asm volatile("red.global.add.v4.f32 [%0], {%1, %2, %3, %4};"
                 :: "l"(p), "f"(v.x * w), "f"(v.y * w), "f"(v.z * w), "f"(v.w * w)
                 : "memory");
}

// ---------------------------------------------------------------------------
// Kernel 5: out = out * in_deg^-1/2 + bias   (in place, one float4 per thread)
// ---------------------------------------------------------------------------
__global__ void k_final(float* __restrict__ out, const float* __restrict__ bias) {
    int gid = blockIdx.x * blockDim.x + threadIdx.x;
    const int total4 = NN * KOUT / 4;
    if (gid >= total4) return;
    int node = gid >> 5;        // 32 float4 per node row
    int c4 = gid & 31;
    float s = rsqrtf((float)max(g_incnt[node], 1));
    float4 v = *reinterpret_cast<float4*>(&out[gid * 4]);
    float4 b = *reinterpret_cast<const float4*>(&bias[c4 * 4]);
    v.x = v.x * s + b.x;
    v.y = v.y * s + b.y;
    v.z = v.z * s + b.z;
    v.w = v.w * s + b.w;
    *reinterpret_cast<float4*>(&out[gid * 4]) = v;
}

// ---------------------------------------------------------------------------
extern "C" void kernel_launch(void* const* d_in, const int* in_sizes, int n_in,
                              void* d_out, int out_size) {
    const float* feat   = (const float*)d_in[0];
    const int*   src    = (const int*)  d_in[1];
    const int*   dst    = (const int*)  d_in[2];
    const float* ew     = (const float*)d_in[3];
    const float* weight = (const float*)d_in[4];
    const float* bias   = (const float*)d_in[5];
    const float* maskr  = (const float*)d_in[6];
    float* out = (float*)d_out;

    k_init<<<2048, 256>>>(out);
    k_deg<<<(EE + 255) / 256, 256>>>(src, dst);
    k_gemm<<<(NN + 127) / 128, 256>>>(feat, weight, maskr);
    long long scatter_threads = (long long)EE * 32;
    k_scatter<<<(unsigned)((scatter_threads + 255) / 256), 256>>>(src, dst, ew, out);
    k_final<<<(NN * KOUT / 4 + 255) / 256, 256>>>(out, bias);
}

// round 3
// speedup vs baseline: 1.4138x; 1.4138x over previous
#include <cuda_runtime.h>

#define NN   100000
#define EE   1600000
#define KIN  256
#define KOUT 128
#define NB_SCAN ((NN + 1023) / 1024)   // 98

// Scratch (allocation-free rule: __device__ globals)
__device__ float  g_featproj[NN * KOUT];   // 51.2 MB projected features
__device__ float2 g_edges[EE];             // dst-bucketed (src_bits, weight)
__device__ int    g_outcnt[NN];
__device__ int    g_incnt[NN];
__device__ int    g_scanpart[NN];
__device__ int    g_rowoff[NN + 1];
__device__ int    g_cursor[NN];
__device__ int    g_blocksum[NB_SCAN];
__device__ int    g_blockoff[NB_SCAN];

// ---------------------------------------------------------------------------
// Kernel 1: zero degree counters
// ---------------------------------------------------------------------------
__global__ void k_init() {
    int i = blockIdx.x * blockDim.x + threadIdx.x;
    int stride = gridDim.x * blockDim.x;
    for (int j = i; j < NN; j += stride) { g_outcnt[j] = 0; g_incnt[j] = 0; }
    if (i == 0) g_rowoff[NN] = EE;
}

// ---------------------------------------------------------------------------
// Kernel 2: degree histograms
// ---------------------------------------------------------------------------
__global__ void k_deg(const int* __restrict__ src, const int* __restrict__ dst) {
    int i = blockIdx.x * blockDim.x + threadIdx.x;
    if (i < EE) {
        atomicAdd(&g_outcnt[src[i]], 1);
        atomicAdd(&g_incnt[dst[i]], 1);
    }
}

// ---------------------------------------------------------------------------
// Exclusive scan of in-degrees (3 kernels)
// ---------------------------------------------------------------------------
__device__ __forceinline__ int warpInclScan(int v) {
#pragma unroll
    for (int o = 1; o < 32; o <<= 1) {
        int n = __shfl_up_sync(0xFFFFFFFFu, v, o);
        if ((threadIdx.x & 31) >= o) v += n;
    }
    return v;
}

__global__ __launch_bounds__(1024) void k_scan1() {
    __shared__ int ws[32];
    int tid = threadIdx.x;
    int i = blockIdx.x * 1024 + tid;
    int lane = tid & 31, wid = tid >> 5;
    int v = (i < NN) ? g_incnt[i] : 0;
    int inc = warpInclScan(v);
    if (lane == 31) ws[wid] = inc;
    __syncthreads();
    if (wid == 0) ws[lane] = warpInclScan(ws[lane]);   // full warp participates
    __syncthreads();
    int excl = inc - v + (wid > 0 ? ws[wid - 1] : 0);
    if (i < NN) g_scanpart[i] = excl;
    if (tid == 1023) g_blocksum[blockIdx.x] = ws[31];
}

__global__ __launch_bounds__(128) void k_scan2() {
    __shared__ int ws[4];
    int tid = threadIdx.x;
    int lane = tid & 31, wid = tid >> 5;
    int v = (tid < NB_SCAN) ? g_blocksum[tid] : 0;
    int inc = warpInclScan(v);
    if (lane == 31) ws[wid] = inc;
    __syncthreads();
    if (wid == 0) {
        // FULL warp runs the scan (shfl mask = all lanes); predicate only the
        // shared-memory access. The previous version deadlocked here.
        int w = (lane < 4) ? ws[lane] : 0;
        w = warpInclScan(w);
        if (lane < 4) ws[lane] = w;
    }
    __syncthreads();
    int excl = inc - v + (wid > 0 ? ws[wid - 1] : 0);
    if (tid < NB_SCAN) g_blockoff[tid] = excl;
}

__global__ void k_scan3() {
    int i = blockIdx.x * blockDim.x + threadIdx.x;
    if (i < NN) {
        int off = g_scanpart[i] + g_blockoff[i >> 10];
        g_rowoff[i] = off;
        g_cursor[i] = off;
    }
}

// ---------------------------------------------------------------------------
// Kernel: bucket edges by dst into contiguous segments (packed src+weight)
// ---------------------------------------------------------------------------
__global__ void k_bucket(const int* __restrict__ src, const int* __restrict__ dst,
                         const float* __restrict__ ew) {
    int e = blockIdx.x * blockDim.x + threadIdx.x;
    if (e < EE) {
        int d = dst[e];
        int pos = atomicAdd(&g_cursor[d], 1);
        g_edges[pos] = make_float2(__int_as_float(src[e]), ew[e]);
    }
}

// ---------------------------------------------------------------------------
// Kernel: FP32 SGEMM  g_featproj = diag(out_deg^-1/2) * feat @ (mask>0.5)*W
// ---------------------------------------------------------------------------
__global__ __launch_bounds__(256) void k_gemm(const float* __restrict__ feat,
                                              const float* __restrict__ weight,
                                              const float* __restrict__ maskr) {
    __shared__ float As[8][128];
    __shared__ float Bs[8][128];

    const int tid = threadIdx.x;
    const int blockRow = blockIdx.x * 128;

    const int arow = tid >> 1;
    const int acol = (tid & 1) * 4;
    const int grow = blockRow + arow;
    float scale = 0.f;
    if (grow < NN) scale = rsqrtf((float)max(g_outcnt[grow], 1));

    const int brow = tid >> 5;
    const int bcol = (tid & 31) * 4;
    const int ty = tid >> 4;
    const int tx = tid & 15;

    float acc[8][8];
#pragma unroll
    for (int i = 0; i < 8; i++)
#pragma unroll
        for (int j = 0; j < 8; j++) acc[i][j] = 0.f;

    for (int k0 = 0; k0 < KIN; k0 += 8) {
        float4 a = make_float4(0.f, 0.f, 0.f, 0.f);
        if (grow < NN)
            a = *reinterpret_cast<const float4*>(&feat[grow * KIN + k0 + acol]);
        As[acol + 0][arow] = a.x * scale;
        As[acol + 1][arow] = a.y * scale;
        As[acol + 2][arow] = a.z * scale;
        As[acol + 3][arow] = a.w * scale;

        float4 w4 = *reinterpret_cast<const float4*>(&weight[(k0 + brow) * KOUT + bcol]);
        float4 m4 = *reinterpret_cast<const float4*>(&maskr [(k0 + brow) * KOUT + bcol]);
        w4.x = (m4.x > 0.5f) ? w4.x : 0.f;
        w4.y = (m4.y > 0.5f) ? w4.y : 0.f;
        w4.z = (m4.z > 0.5f) ? w4.z : 0.f;
        w4.w = (m4.w > 0.5f) ? w4.w : 0.f;
        *reinterpret_cast<float4*>(&Bs[brow][bcol]) = w4;

        __syncthreads();

#pragma unroll
        for (int k = 0; k < 8; k++) {
            float ar[8], br[8];
            *reinterpret_cast<float4*>(&ar[0]) = *reinterpret_cast<const float4*>(&As[k][ty * 8]);
            *reinterpret_cast<float4*>(&ar[4]) = *reinterpret_cast<const float4*>(&As[k][ty * 8 + 4]);
            *reinterpret_cast<float4*>(&br[0]) = *reinterpret_cast<const float4*>(&Bs[k][tx * 8]);
            *reinterpret_cast<float4*>(&br[4]) = *reinterpret_cast<const float4*>(&Bs[k][tx * 8 + 4]);
#pragma unroll
            for (int i = 0; i < 8; i++)
#pragma unroll
                for (int j = 0; j < 8; j++)
                    acc[i][j] = fmaf(ar[i], br[j], acc[i][j]);
        }
        __syncthreads();
    }

#pragma unroll
    for (int i = 0; i < 8; i++) {
        int r = blockRow + ty * 8 + i;
        if (r < NN) {
            *reinterpret_cast<float4*>(&g_featproj[r * KOUT + tx * 8]) =
                make_float4(acc[i][0], acc[i][1], acc[i][2], acc[i][3]);
            *reinterpret_cast<float4*>(&g_featproj[r * KOUT + tx * 8 + 4]) =
                make_float4(acc[i][4], acc[i][5], acc[i][6], acc[i][7]);
        }
    }
}

// ---------------------------------------------------------------------------
// Kernel: aggregation. One warp per dst node: loop contiguous edge segment,
// coalesced 512B gathers, register accumulation, single store with fused
// in_deg^-1/2 scaling + bias. No fp atomics.
// ---------------------------------------------------------------------------
__global__ __launch_bounds__(256) void k_agg(float* __restrict__ out,
                                             const float* __restrict__ bias) {
    int node = blockIdx.x * 8 + (threadIdx.x >> 5);
    int lane = threadIdx.x & 31;
    if (node >= NN) return;

    int beg = g_rowoff[node];
    int end = g_rowoff[node + 1];

    float4 acc = make_float4(0.f, 0.f, 0.f, 0.f);
    int e = beg;
    for (; e + 1 < end; e += 2) {
        float2 e0 = g_edges[e];
        float2 e1 = g_edges[e + 1];
        int s0 = __float_as_int(e0.x);
        int s1 = __float_as_int(e1.x);
        float4 v0 = *reinterpret_cast<const float4*>(&g_featproj[s0 * KOUT + lane * 4]);
        float4 v1 = *reinterpret_cast<const float4*>(&g_featproj[s1 * KOUT + lane * 4]);
        acc.x = fmaf(e0.y, v0.x, fmaf(e1.y, v1.x, acc.x));
        acc.y = fmaf(e0.y, v0.y, fmaf(e1.y, v1.y, acc.y));
        acc.z = fmaf(e0.y, v0.z, fmaf(e1.y, v1.z, acc.z));
        acc.w = fmaf(e0.y, v0.w, fmaf(e1.y, v1.w, acc.w));
    }
    if (e < end) {
        float2 e0 = g_edges[e];
        int s0 = __float_as_int(e0.x);
        float4 v0 = *reinterpret_cast<const float4*>(&g_featproj[s0 * KOUT + lane * 4]);
        acc.x = fmaf(e0.y, v0.x, acc.x);
        acc.y = fmaf(e0.y, v0.y, acc.y);
        acc.z = fmaf(e0.y, v0.z, acc.z);
        acc.w = fmaf(e0.y, v0.w, acc.w);
    }

    float sc = rsqrtf((float)max(end - beg, 1));
    float4 b = *reinterpret_cast<const float4*>(&bias[lane * 4]);
    acc.x = fmaf(acc.x, sc, b.x);
    acc.y = fmaf(acc.y, sc, b.y);
    acc.z = fmaf(acc.z, sc, b.z);
    acc.w = fmaf(acc.w, sc, b.w);
    *reinterpret_cast<float4*>(&out[node * KOUT + lane * 4]) = acc;
}

// ---------------------------------------------------------------------------
extern "C" void kernel_launch(void* const* d_in, const int* in_sizes, int n_in,
                              void* d_out, int out_size) {
    const float* feat   = (const float*)d_in[0];
    const int*   src    = (const int*)  d_in[1];
    const int*   dst    = (const int*)  d_in[2];
    const float* ew     = (const float*)d_in[3];
    const float* weight = (const float*)d_in[4];
    const float* bias   = (const float*)d_in[5];
    const float* maskr  = (const float*)d_in[6];
    float* out = (float*)d_out;

    k_init<<<256, 256>>>();
    k_deg<<<(EE + 255) / 256, 256>>>(src, dst);
    k_scan1<<<NB_SCAN, 1024>>>();
    k_scan2<<<1, 128>>>();
    k_scan3<<<(NN + 255) / 256, 256>>>();
    k_bucket<<<(EE + 255) / 256, 256>>>(src, dst, ew);
    k_gemm<<<(NN + 127) / 128, 256>>>(feat, weight, maskr);
    k_agg<<<(NN + 7) / 8, 256>>>(out, bias);
}

// round 4
// speedup vs baseline: 1.4427x; 1.0204x over previous
#include <cuda_runtime.h>

#define NN   100000
#define EE   1600000
#define KIN  256
#define KOUT 128
#define NB_SCAN ((NN + 1023) / 1024)   // 98

// Scratch (allocation-free rule: __device__ globals)
__device__ float  g_featproj[NN * KOUT];   // 51.2 MB projected features
__device__ float2 g_edges[EE];             // dst-bucketed (src_bits, weight)
__device__ int    g_outcnt[NN];
__device__ int    g_incnt[NN];
__device__ int    g_scanpart[NN];
__device__ int    g_rowoff[NN + 1];
__device__ int    g_cursor[NN];
__device__ int    g_blocksum[NB_SCAN];
__device__ int    g_blockoff[NB_SCAN];

// ---------------------------------------------------------------------------
// Kernel 1: zero degree counters
// ---------------------------------------------------------------------------
__global__ void k_init() {
    int i = blockIdx.x * blockDim.x + threadIdx.x;
    int stride = gridDim.x * blockDim.x;
    for (int j = i; j < NN; j += stride) { g_outcnt[j] = 0; g_incnt[j] = 0; }
    if (i == 0) g_rowoff[NN] = EE;
}

// ---------------------------------------------------------------------------
// Kernel 2: degree histograms
// ---------------------------------------------------------------------------
__global__ void k_deg(const int* __restrict__ src, const int* __restrict__ dst) {
    int i = blockIdx.x * blockDim.x + threadIdx.x;
    if (i < EE) {
        atomicAdd(&g_outcnt[src[i]], 1);
        atomicAdd(&g_incnt[dst[i]], 1);
    }
}

// ---------------------------------------------------------------------------
// Exclusive scan of in-degrees (3 kernels)
// ---------------------------------------------------------------------------
__device__ __forceinline__ int warpInclScan(int v) {
#pragma unroll
    for (int o = 1; o < 32; o <<= 1) {
        int n = __shfl_up_sync(0xFFFFFFFFu, v, o);
        if ((threadIdx.x & 31) >= o) v += n;
    }
    return v;
}

__global__ __launch_bounds__(1024) void k_scan1() {
    __shared__ int ws[32];
    int tid = threadIdx.x;
    int i = blockIdx.x * 1024 + tid;
    int lane = tid & 31, wid = tid >> 5;
    int v = (i < NN) ? g_incnt[i] : 0;
    int inc = warpInclScan(v);
    if (lane == 31) ws[wid] = inc;
    __syncthreads();
    if (wid == 0) ws[lane] = warpInclScan(ws[lane]);   // full warp participates
    __syncthreads();
    int excl = inc - v + (wid > 0 ? ws[wid - 1] : 0);
    if (i < NN) g_scanpart[i] = excl;
    if (tid == 1023) g_blocksum[blockIdx.x] = ws[31];
}

__global__ __launch_bounds__(128) void k_scan2() {
    __shared__ int ws[4];
    int tid = threadIdx.x;
    int lane = tid & 31, wid = tid >> 5;
    int v = (tid < NB_SCAN) ? g_blocksum[tid] : 0;
    int inc = warpInclScan(v);
    if (lane == 31) ws[wid] = inc;
    __syncthreads();
    if (wid == 0) {
        int w = (lane < 4) ? ws[lane] : 0;   // full warp runs the shfl scan
        w = warpInclScan(w);
        if (lane < 4) ws[lane] = w;
    }
    __syncthreads();
    int excl = inc - v + (wid > 0 ? ws[wid - 1] : 0);
    if (tid < NB_SCAN) g_blockoff[tid] = excl;
}

__global__ void k_scan3() {
    int i = blockIdx.x * blockDim.x + threadIdx.x;
    if (i < NN) {
        int off = g_scanpart[i] + g_blockoff[i >> 10];
        g_rowoff[i] = off;
        g_cursor[i] = off;
    }
}

// ---------------------------------------------------------------------------
// Kernel: bucket edges by dst into contiguous segments (packed src+weight)
// ---------------------------------------------------------------------------
__global__ void k_bucket(const int* __restrict__ src, const int* __restrict__ dst,
                         const float* __restrict__ ew) {
    int e = blockIdx.x * blockDim.x + threadIdx.x;
    if (e < EE) {
        int d = dst[e];
        int pos = atomicAdd(&g_cursor[d], 1);
        g_edges[pos] = make_float2(__int_as_float(src[e]), ew[e]);
    }
}

// ---------------------------------------------------------------------------
// Kernel: FP32 SGEMM via packed fma.rn.f32x2 (FFMA2 — 2 FMA/instr)
// g_featproj = diag(out_deg^-1/2) * feat @ (mask>0.5)*W
// BM=128, BN=128(=KOUT), BK=8, 256 threads, 8x8 per thread (8x4 packed)
// ---------------------------------------------------------------------------
__global__ __launch_bounds__(256) void k_gemm(const float* __restrict__ feat,
                                              const float* __restrict__ weight,
                                              const float* __restrict__ maskr) {
    __shared__ float As[8][128];
    __shared__ float Bs[8][128];

    const int tid = threadIdx.x;
    const int blockRow = blockIdx.x * 128;

    const int arow = tid >> 1;
    const int acol = (tid & 1) * 4;
    const int grow = blockRow + arow;
    float scale = 0.f;
    if (grow < NN) scale = rsqrtf((float)max(g_outcnt[grow], 1));

    const int brow = tid >> 5;
    const int bcol = (tid & 31) * 4;
    const int ty = tid >> 4;
    const int tx = tid & 15;

    // packed accumulators: acc2[i][j] holds columns {2j, 2j+1} of row i
    unsigned long long acc2[8][4];
#pragma unroll
    for (int i = 0; i < 8; i++)
#pragma unroll
        for (int j = 0; j < 4; j++) acc2[i][j] = 0ULL;

    for (int k0 = 0; k0 < KIN; k0 += 8) {
        float4 a = make_float4(0.f, 0.f, 0.f, 0.f);
        if (grow < NN)
            a = *reinterpret_cast<const float4*>(&feat[grow * KIN + k0 + acol]);
        As[acol + 0][arow] = a.x * scale;
        As[acol + 1][arow] = a.y * scale;
        As[acol + 2][arow] = a.z * scale;
        As[acol + 3][arow] = a.w * scale;

        float4 w4 = *reinterpret_cast<const float4*>(&weight[(k0 + brow) * KOUT + bcol]);
        float4 m4 = *reinterpret_cast<const float4*>(&maskr [(k0 + brow) * KOUT + bcol]);
        w4.x = (m4.x > 0.5f) ? w4.x : 0.f;
        w4.y = (m4.y > 0.5f) ? w4.y : 0.f;
        w4.z = (m4.z > 0.5f) ? w4.z : 0.f;
        w4.w = (m4.w > 0.5f) ? w4.w : 0.f;
        *reinterpret_cast<float4*>(&Bs[brow][bcol]) = w4;

        __syncthreads();

#pragma unroll
        for (int k = 0; k < 8; k++) {
            float ar[8], br[8];
            *reinterpret_cast<float4*>(&ar[0]) = *reinterpret_cast<const float4*>(&As[k][ty * 8]);
            *reinterpret_cast<float4*>(&ar[4]) = *reinterpret_cast<const float4*>(&As[k][ty * 8 + 4]);
            *reinterpret_cast<float4*>(&br[0]) = *reinterpret_cast<const float4*>(&Bs[k][tx * 8]);
            *reinterpret_cast<float4*>(&br[4]) = *reinterpret_cast<const float4*>(&Bs[k][tx * 8 + 4]);

            unsigned long long br2[4], ar2[8];
#pragma unroll
            for (int j = 0; j < 4; j++)
                asm("mov.b64 %0, {%1, %2};" : "=l"(br2[j]) : "f"(br[2 * j]), "f"(br[2 * j + 1]));
#pragma unroll
            for (int i = 0; i < 8; i++)
                asm("mov.b64 %0, {%1, %2};" : "=l"(ar2[i]) : "f"(ar[i]), "f"(ar[i]));

#pragma unroll
            for (int i = 0; i < 8; i++)
#pragma unroll
                for (int j = 0; j < 4; j++)
                    asm("fma.rn.f32x2 %0, %1, %2, %0;"
                        : "+l"(acc2[i][j]) : "l"(ar2[i]), "l"(br2[j]));
        }
        __syncthreads();
    }

#pragma unroll
    for (int i = 0; i < 8; i++) {
        int r = blockRow + ty * 8 + i;
        if (r < NN) {
            float c[8];
#pragma unroll
            for (int j = 0; j < 4; j++)
                asm("mov.b64 {%0, %1}, %2;" : "=f"(c[2 * j]), "=f"(c[2 * j + 1]) : "l"(acc2[i][j]));
            *reinterpret_cast<float4*>(&g_featproj[r * KOUT + tx * 8]) =
                make_float4(c[0], c[1], c[2], c[3]);
            *reinterpret_cast<float4*>(&g_featproj[r * KOUT + tx * 8 + 4]) =
                make_float4(c[4], c[5], c[6], c[7]);
        }
    }
}

// ---------------------------------------------------------------------------
// Kernel: aggregation. One warp per dst node: loop contiguous edge segment,
// coalesced 512B gathers, register accumulation, single store with fused
// in_deg^-1/2 scaling + bias. No fp atomics.
// ---------------------------------------------------------------------------
__global__ __launch_bounds__(256) void k_agg(float* __restrict__ out,
                                             const float* __restrict__ bias) {
    int node = blockIdx.x * 8 + (threadIdx.x >> 5);
    int lane = threadIdx.x & 31;
    if (node >= NN) return;

    int beg = g_rowoff[node];
    int end = g_rowoff[node + 1];

    float4 acc = make_float4(0.f, 0.f, 0.f, 0.f);
    int e = beg;
    for (; e + 1 < end; e += 2) {
        float2 e0 = g_edges[e];
        float2 e1 = g_edges[e + 1];
        int s0 = __float_as_int(e0.x);
        int s1 = __float_as_int(e1.x);
        float4 v0 = *reinterpret_cast<const float4*>(&g_featproj[s0 * KOUT + lane * 4]);
        float4 v1 = *reinterpret_cast<const float4*>(&g_featproj[s1 * KOUT + lane * 4]);
        acc.x = fmaf(e0.y, v0.x, fmaf(e1.y, v1.x, acc.x));
        acc.y = fmaf(e0.y, v0.y, fmaf(e1.y, v1.y, acc.y));
        acc.z = fmaf(e0.y, v0.z, fmaf(e1.y, v1.z, acc.z));
        acc.w = fmaf(e0.y, v0.w, fmaf(e1.y, v1.w, acc.w));
    }
    if (e < end) {
        float2 e0 = g_edges[e];
        int s0 = __float_as_int(e0.x);
        float4 v0 = *reinterpret_cast<const float4*>(&g_featproj[s0 * KOUT + lane * 4]);
        acc.x = fmaf(e0.y, v0.x, acc.x);
        acc.y = fmaf(e0.y, v0.y, acc.y);
        acc.z = fmaf(e0.y, v0.z, acc.z);
        acc.w = fmaf(e0.y, v0.w, acc.w);
    }

    float sc = rsqrtf((float)max(end - beg, 1));
    float4 b = *reinterpret_cast<const float4*>(&bias[lane * 4]);
    acc.x = fmaf(acc.x, sc, b.x);
    acc.y = fmaf(acc.y, sc, b.y);
    acc.z = fmaf(acc.z, sc, b.z);
    acc.w = fmaf(acc.w, sc, b.w);
    *reinterpret_cast<float4*>(&out[node * KOUT + lane * 4]) = acc;
}

// ---------------------------------------------------------------------------
extern "C" void kernel_launch(void* const* d_in, const int* in_sizes, int n_in,
                              void* d_out, int out_size) {
    const float* feat   = (const float*)d_in[0];
    const int*   src    = (const int*)  d_in[1];
    const int*   dst    = (const int*)  d_in[2];
    const float* ew     = (const float*)d_in[3];
    const float* weight = (const float*)d_in[4];
    const float* bias   = (const float*)d_in[5];
    const float* maskr  = (const float*)d_in[6];
    float* out = (float*)d_out;

    k_init<<<256, 256>>>();
    k_deg<<<(EE + 255) / 256, 256>>>(src, dst);
    k_scan1<<<NB_SCAN, 1024>>>();
    k_scan2<<<1, 128>>>();
    k_scan3<<<(NN + 255) / 256, 256>>>();
    k_bucket<<<(EE + 255) / 256, 256>>>(src, dst, ew);
    k_gemm<<<(NN + 127) / 128, 256>>>(feat, weight, maskr);
    k_agg<<<(NN + 7) / 8, 256>>>(out, bias);
}